// round 6
// baseline (speedup 1.0000x reference)
#include <cuda_runtime.h>
#include <cuda_fp16.h>
#include <cstdint>

// ============================================================================
// dims
// ============================================================================
#define B_DIM 32
#define F_DIM 1024
#define L_DIM 1000
#define N_DIM 2048
#define LPAD  1024

// GEMM tiling (per batch: M=N_DIM rows n, N=L cols l, K=F)
#define TM 128
#define TN 128
#define KC 32                    // K halves per k-chunk (one m16n8k32 sp step)
#define STAGES 4
#define KITERS (F_DIM / KC)      // 32

// SMEM strides
#define RSTRIDE_A 48             // compressed A row: 32B data, pad to 48B (conflict-free ldmatrix)
#define RSTRIDE_B 80             // B row: 64B data, pad to 80B
#define A_STAGE_BYTES (TM * RSTRIDE_A)                     // 6144
#define B_STAGE_BYTES (TN * RSTRIDE_B)                     // 10240
#define META_STAGE_BYTES 512                               // 8 blk x 8 r x 2 x u32
#define STAGE_BYTES (A_STAGE_BYTES + B_STAGE_BYTES + META_STAGE_BYTES) // 16896
#define SMEM_BYTES (STAGES * STAGE_BYTES)                  // 67584

#define OVF_MAX 8192

// ============================================================================
// device scratch (static globals: allocation-guard safe)
// ============================================================================
__device__ __align__(1024) __half g_A  [(size_t)N_DIM * F_DIM];        // 4 MB dense fp16 A
__device__ __align__(1024) __half g_Av [(size_t)N_DIM * (F_DIM / 2)];  // 2 MB compressed A
__device__ __align__(1024) uint32_t g_EMeta[(size_t)KITERS * 128 * 8 * 2]; // 256 KB metadata
__device__ __align__(1024) __half g_Xt[(size_t)B_DIM * LPAD * F_DIM];  // 67 MB
__device__ unsigned g_ovf_cnt;
__device__ int   g_ovf_n[OVF_MAX];
__device__ int   g_ovf_f[OVF_MAX];
__device__ float g_ovf_v[OVF_MAX];

// ============================================================================
// helpers
// ============================================================================
__device__ __forceinline__ uint32_t smem_u32(const void* p) {
    uint32_t a;
    asm("{ .reg .u64 t; cvta.to.shared.u64 t, %1; cvt.u32.u64 %0, t; }"
        : "=r"(a) : "l"(p));
    return a;
}

#define CP_ASYNC16(dst, src) \
    asm volatile("cp.async.cg.shared.global [%0], [%1], 16;" \
                 :: "r"(dst), "l"(src) : "memory")
#define CP_COMMIT() asm volatile("cp.async.commit_group;" ::: "memory")
#define CP_WAIT(n)  asm volatile("cp.async.wait_group %0;" :: "n"(n) : "memory")

#define LDSM_X4(r0, r1, r2, r3, addr) \
    asm volatile("ldmatrix.sync.aligned.m8n8.x4.shared.b16 {%0,%1,%2,%3}, [%4];" \
                 : "=r"(r0), "=r"(r1), "=r"(r2), "=r"(r3) : "r"(addr))

// sparse fp16 MMA: A 16x32 2:4-compressed (4 regs), B 32x8 (4 regs), selector 0
__device__ __forceinline__ void mma_sp(float d[4], const uint32_t a[4],
                                       uint32_t b0, uint32_t b1,
                                       uint32_t b2, uint32_t b3, uint32_t e) {
    asm volatile(
        "mma.sp::ordered_metadata.sync.aligned.m16n8k32.row.col.f32.f16.f16.f32 "
        "{%0,%1,%2,%3}, {%4,%5,%6,%7}, {%8,%9,%10,%11}, {%0,%1,%2,%3}, %12, 0x0;"
        : "+f"(d[0]), "+f"(d[1]), "+f"(d[2]), "+f"(d[3])
        : "r"(a[0]), "r"(a[1]), "r"(a[2]), "r"(a[3]),
          "r"(b0), "r"(b1), "r"(b2), "r"(b3), "r"(e));
}

// ============================================================================
// prep 0: reset overflow counter (graph-replay safe)
// ============================================================================
__global__ void reset_cnt_kernel() { g_ovf_cnt = 0; }

// ============================================================================
// prep 1: dense A[n][f] = fp16(C[f][n] * W[n])
// ============================================================================
__global__ void prep_a_kernel(const float* __restrict__ C,
                              const float* __restrict__ W) {
    __shared__ float tile[32][33];
    const int n0 = blockIdx.x * 32;
    const int f0 = blockIdx.y * 32;
    const int tx = threadIdx.x, ty = threadIdx.y;
    const float w = W[n0 + tx];
#pragma unroll
    for (int i = 0; i < 32; i += 8)
        tile[ty + i][tx] = C[(size_t)(f0 + ty + i) * N_DIM + n0 + tx] * w;
    __syncthreads();
    if (tx < 16) {
#pragma unroll
        for (int i = 0; i < 32; i += 8) {
            const int n = n0 + ty + i;
            __half2 v = __floats2half2_rn(tile[2 * tx][ty + i],
                                          tile[2 * tx + 1][ty + i]);
            *reinterpret_cast<__half2*>(g_A + (size_t)n * F_DIM + f0 + 2 * tx) = v;
        }
    }
}

// ============================================================================
// prep 2: 2:4 compress A -> g_Av + g_EMeta + overflow list
//   thread = (blk 0..127, r 0..7, kc 0..31); handles row pair (16blk+r, +8)
// ============================================================================
__global__ void compress_kernel(const float* __restrict__ W) {
    const int idx = blockIdx.x * blockDim.x + threadIdx.x;
    if (idx >= 128 * 8 * KITERS) return;
    const int kc  = idx & 31;
    const int r   = (idx >> 5) & 7;
    const int blk = idx >> 8;

    uint32_t mlo[2], mhi[2];
#pragma unroll
    for (int h = 0; h < 2; h++) {
        const int n = blk * 16 + r + h * 8;
        const __half* row = g_A + (size_t)n * F_DIM + kc * KC;
        __half* outp = g_Av + (size_t)n * (F_DIM / 2) + kc * 16;
        uint32_t metlo = 0, methi = 0;
#pragma unroll
        for (int g2 = 0; g2 < 8; g2++) {
            int ids[4]; __half vals[4]; int cnt = 0;
#pragma unroll
            for (int j = 0; j < 4; j++) {
                __half v = row[4 * g2 + j];
                if (__half_as_ushort(v) & 0x7FFF) {
                    ids[cnt] = j; vals[cnt] = v; cnt++;
                }
            }
            int i0, i1; __half v0, v1;
            const __half hz = __ushort_as_half(0);
            if (cnt == 0)      { i0 = 0; i1 = 1; v0 = hz; v1 = hz; }
            else if (cnt == 1) {
                if (ids[0] < 3) { i0 = ids[0]; v0 = vals[0]; i1 = 3; v1 = hz; }
                else            { i0 = 2; v0 = hz; i1 = 3; v1 = vals[0]; }
            } else {
                i0 = ids[0]; v0 = vals[0]; i1 = ids[1]; v1 = vals[1];
                for (int o = 2; o < cnt; o++) {
                    unsigned slot = atomicAdd(&g_ovf_cnt, 1u);
                    if (slot < OVF_MAX) {
                        g_ovf_n[slot] = n;
                        g_ovf_f[slot] = kc * KC + 4 * g2 + ids[o];
                        g_ovf_v[slot] = W[n];
                    }
                }
            }
            outp[2 * g2]     = v0;
            outp[2 * g2 + 1] = v1;
            uint32_t nib = (uint32_t)i0 | ((uint32_t)i1 << 2);
            if (g2 < 4) metlo |= nib << (4 * g2);
            else        methi |= nib << (4 * (g2 - 4));
        }
        mlo[h] = metlo; mhi[h] = methi;
    }
    const size_t base = (((size_t)kc * 128 + blk) * 8 + r) * 2;
    g_EMeta[base + 0] = mlo[0] | (mlo[1] << 16);   // k[0:16): rows (r, r+8)
    g_EMeta[base + 1] = mhi[0] | (mhi[1] << 16);   // k[16:32)
}

// ============================================================================
// prep 3: Xt[b][l][f] = fp16(X[b][f][l]), l zero-padded to 1024
// ============================================================================
__global__ void prep_x_kernel(const float* __restrict__ X) {
    __shared__ float tile[32][33];
    const int l0 = blockIdx.x * 32;
    const int f0 = blockIdx.y * 32;
    const int b  = blockIdx.z;
    const int tx = threadIdx.x, ty = threadIdx.y;
    const float* Xb = X + (size_t)b * F_DIM * L_DIM;
#pragma unroll
    for (int i = 0; i < 32; i += 8) {
        int l = l0 + tx;
        tile[ty + i][tx] = (l < L_DIM)
            ? Xb[(size_t)(f0 + ty + i) * L_DIM + l] : 0.0f;
    }
    __syncthreads();
    __half* Xtb = g_Xt + (size_t)b * LPAD * F_DIM;
    if (tx < 16) {
#pragma unroll
        for (int i = 0; i < 32; i += 8) {
            const int l = l0 + ty + i;
            __half2 v = __floats2half2_rn(tile[2 * tx][ty + i],
                                          tile[2 * tx + 1][ty + i]);
            *reinterpret_cast<__half2*>(Xtb + (size_t)l * F_DIM + f0 + 2 * tx) = v;
        }
    }
}

// ============================================================================
// sparse GEMM: out[b, n0:+128, l0:+128] = A(2:4) x Xt^T
//   128 threads = 4 warps: 2(m) x 2(n), warp tile 64 x 64
// ============================================================================
__global__ void __launch_bounds__(128, 2)
gemm_kernel(float* __restrict__ out) {
    extern __shared__ __align__(128) char smem[];
    const uint32_t sbase = smem_u32(smem);

    const int tid = threadIdx.x;
    const int wid = tid >> 5;
    const int lid = tid & 31;
    const int g = lid >> 2;
    const int t = lid & 3;

    const int wm = wid & 1;
    const int wn = wid >> 1;

    const int n0 = blockIdx.x * TM;
    const int l0 = blockIdx.y * TN;
    const int b  = blockIdx.z;

    const __half* Avbase = g_Av + (size_t)n0 * (F_DIM / 2);
    const __half* Bbase  = g_Xt + ((size_t)b * LPAD + l0) * F_DIM;
    const uint32_t* Mbase = g_EMeta;   // [kc][128][8][2]
    const int nb0 = 8 * blockIdx.x;    // first 16-row block index of this tile

    float d[4][8][4];
#pragma unroll
    for (int mi = 0; mi < 4; mi++)
#pragma unroll
        for (int ni = 0; ni < 8; ni++)
#pragma unroll
            for (int r = 0; r < 4; r++) d[mi][ni][r] = 0.0f;

    // B cp.async mapping (128 rows x 4 chunks of 16B)
    const int c_row = tid >> 2;
    const int c_cb  = tid & 3;

    auto load_stage = [&](int s, int k) {
        const uint32_t sa = sbase + s * STAGE_BYTES;
        const uint32_t sb = sa + A_STAGE_BYTES;
        const uint32_t sm = sb + B_STAGE_BYTES;
        // A: row tid, 2 x 16B chunks (32B compressed per k32)
        const __half* asrc = Avbase + (size_t)tid * (F_DIM / 2) + k * 16;
        CP_ASYNC16(sa + tid * RSTRIDE_A,      asrc);
        CP_ASYNC16(sa + tid * RSTRIDE_A + 16, asrc + 8);
        // B: 128 rows x 64B
        const int k0 = k * KC;
#pragma unroll
        for (int i = 0; i < 4; i++) {
            int row = c_row + i * 32;
            CP_ASYNC16(sb + row * RSTRIDE_B + c_cb * 16,
                       Bbase + (size_t)row * F_DIM + k0 + c_cb * 8);
        }
        // meta: 512B = 32 x 16B
        if (tid < 32) {
            const uint32_t* msrc = Mbase + ((size_t)k * 128 + nb0) * 16 + tid * 4;
            CP_ASYNC16(sm + tid * 16, msrc);
        }
        CP_COMMIT();
    };

    load_stage(0, 0);
    load_stage(1, 1);
    load_stage(2, 2);

    const int lrow = lid & 15;
    const int lchunk = (lid >> 4) * 16;
    const int ehalf = lid & 1;           // T0/T2 -> k-lo word, T1/T3 -> k-hi word

    for (int k = 0; k < KITERS; k++) {
        CP_WAIT(2);
        __syncthreads();
        if (k + 3 < KITERS) load_stage((k + 3) % STAGES, k + 3);

        const uint32_t sa = sbase + (k % STAGES) * STAGE_BYTES;
        const uint32_t sb = sa + A_STAGE_BYTES;
        const uint32_t sm = sb + B_STAGE_BYTES;

        // A fragments (compressed 16x16 per mi)
        uint32_t af[4][4];
#pragma unroll
        for (int mi = 0; mi < 4; mi++) {
            uint32_t addr = sa + (wm * 64 + mi * 16 + lrow) * RSTRIDE_A + lchunk;
            LDSM_X4(af[mi][0], af[mi][1], af[mi][2], af[mi][3], addr);
        }
        // B fragments: k-lo and k-hi 16-halves
        uint32_t blo[8][2], bhi[8][2];
#pragma unroll
        for (int p = 0; p < 4; p++) {
            uint32_t addr = sb + (wn * 64 + p * 16 + lrow) * RSTRIDE_B + lchunk;
            uint32_t m0, m1, m2, m3;
            LDSM_X4(m0, m1, m2, m3, addr);
            blo[2 * p][0] = m0; blo[2 * p][1] = m2;
            blo[2 * p + 1][0] = m1; blo[2 * p + 1][1] = m3;
            uint32_t q0, q1, q2, q3;
            LDSM_X4(q0, q1, q2, q3, addr + 32);
            bhi[2 * p][0] = q0; bhi[2 * p][1] = q2;
            bhi[2 * p + 1][0] = q1; bhi[2 * p + 1][1] = q3;
        }
        // metadata words
        uint32_t ev[4];
#pragma unroll
        for (int mi = 0; mi < 4; mi++) {
            uint32_t maddr = sm + (((wm * 4 + mi) * 8 + g) * 2 + ehalf) * 4;
            asm volatile("ld.shared.b32 %0, [%1];" : "=r"(ev[mi]) : "r"(maddr));
        }
#pragma unroll
        for (int mi = 0; mi < 4; mi++)
#pragma unroll
            for (int ni = 0; ni < 8; ni++)
                mma_sp(d[mi][ni], af[mi],
                       blo[ni][0], blo[ni][1], bhi[ni][0], bhi[ni][1], ev[mi]);
    }

    // ---- epilogue: direct global float2 stores ----
#pragma unroll
    for (int mi = 0; mi < 4; mi++) {
        const int row = n0 + wm * 64 + mi * 16 + g;
        float* r0 = out + ((size_t)b * N_DIM + row) * L_DIM;
        float* r1 = r0 + 8 * L_DIM;
#pragma unroll
        for (int ni = 0; ni < 8; ni++) {
            const int l = l0 + wn * 64 + ni * 8 + 2 * t;
            if (l < L_DIM) {
                *reinterpret_cast<float2*>(r0 + l) =
                    make_float2(d[mi][ni][0], d[mi][ni][1]);
                *reinterpret_cast<float2*>(r1 + l) =
                    make_float2(d[mi][ni][2], d[mi][ni][3]);
            }
        }
    }
}

// ============================================================================
// fixup: out[b, n, :] += val * X[b, f, :] for each overflow element
// ============================================================================
__global__ void fixup_kernel(float* __restrict__ out,
                             const float* __restrict__ X) {
    const unsigned cnt = *((volatile unsigned*)&g_ovf_cnt);
    const unsigned e = blockIdx.x;
    if (e >= cnt || e >= OVF_MAX) return;
    const int b = blockIdx.y;
    const int n = g_ovf_n[e];
    const int f = g_ovf_f[e];
    const float v = g_ovf_v[e];
    const float* xr = X + ((size_t)b * F_DIM + f) * L_DIM;
    float* orow = out + ((size_t)b * N_DIM + n) * L_DIM;
    for (int l = threadIdx.x; l < L_DIM; l += 256)
        atomicAdd(orow + l, v * xr[l]);
}

// ============================================================================
// host
// ============================================================================
extern "C" void kernel_launch(void* const* d_in, const int* in_sizes, int n_in,
                              void* d_out, int out_size) {
    const float* X = (const float*)d_in[0];
    const float* C = (const float*)d_in[1];
    const float* W = (const float*)d_in[2];
    for (int i = 0; i < n_in; i++) {
        if (in_sizes[i] == B_DIM * F_DIM * L_DIM) X = (const float*)d_in[i];
        else if (in_sizes[i] == F_DIM * N_DIM)    C = (const float*)d_in[i];
        else if (in_sizes[i] == N_DIM)            W = (const float*)d_in[i];
    }

    cudaFuncSetAttribute(gemm_kernel,
                         cudaFuncAttributeMaxDynamicSharedMemorySize, SMEM_BYTES);

    reset_cnt_kernel<<<1, 1>>>();
    prep_a_kernel<<<dim3(N_DIM / 32, F_DIM / 32), dim3(32, 8)>>>(C, W);
    compress_kernel<<<(128 * 8 * KITERS + 255) / 256, 256>>>(W);
    prep_x_kernel<<<dim3(LPAD / 32, F_DIM / 32, B_DIM), dim3(32, 8)>>>(X);
    gemm_kernel<<<dim3(N_DIM / TM, LPAD / TN, B_DIM), 128, SMEM_BYTES>>>(
        (float*)d_out);
    fixup_kernel<<<dim3(OVF_MAX, B_DIM), 256>>>((float*)d_out, X);
}

// round 7
// speedup vs baseline: 1.3761x; 1.3761x over previous
#include <cuda_runtime.h>
#include <cuda_fp16.h>
#include <cstdint>

// ============================================================================
// dims
// ============================================================================
#define B_DIM 32
#define F_DIM 1024
#define L_DIM 1000
#define N_DIM 2048
#define LPAD  1024

// GEMM tiling (per batch: M=N_DIM rows n, N=L cols l, K=F)
#define TM 128
#define TN 128
#define KC 64                    // K halves per chunk (128B rows)
#define STAGES 3
#define KITERS (F_DIM / KC)      // 16

// SMEM: row stride 144B (128B data + 16B pad) -> ldmatrix windows at banks 4r
#define RSTRIDE_B 144
#define A_STAGE_BYTES (TM * RSTRIDE_B)                     // 18432
#define B_STAGE_BYTES (TN * RSTRIDE_B)                     // 18432
#define STAGE_BYTES (A_STAGE_BYTES + B_STAGE_BYTES)        // 36864
#define SMEM_BYTES (STAGES * STAGE_BYTES)                  // 110592

// ============================================================================
// device scratch (static globals: allocation-guard safe)
// ============================================================================
__device__ __align__(1024) __half g_A [(size_t)N_DIM * F_DIM];        // 4 MB
__device__ __align__(1024) __half g_Xt[(size_t)B_DIM * LPAD * F_DIM]; // 67 MB

// ============================================================================
// helpers
// ============================================================================
__device__ __forceinline__ uint32_t smem_u32(const void* p) {
    uint32_t a;
    asm("{ .reg .u64 t; cvta.to.shared.u64 t, %1; cvt.u32.u64 %0, t; }"
        : "=r"(a) : "l"(p));
    return a;
}

#define CP_ASYNC16(dst, src) \
    asm volatile("cp.async.cg.shared.global [%0], [%1], 16;" \
                 :: "r"(dst), "l"(src) : "memory")
#define CP_COMMIT() asm volatile("cp.async.commit_group;" ::: "memory")
#define CP_WAIT(n)  asm volatile("cp.async.wait_group %0;" :: "n"(n) : "memory")

#define LDSM_X4(r0, r1, r2, r3, addr) \
    asm volatile("ldmatrix.sync.aligned.m8n8.x4.shared.b16 {%0,%1,%2,%3}, [%4];" \
                 : "=r"(r0), "=r"(r1), "=r"(r2), "=r"(r3) : "r"(addr))

__device__ __forceinline__ void mma_f16(float d[4],
                                        uint32_t a0, uint32_t a1,
                                        uint32_t a2, uint32_t a3,
                                        uint32_t b0, uint32_t b1) {
    asm volatile(
        "mma.sync.aligned.m16n8k16.row.col.f32.f16.f16.f32 "
        "{%0, %1, %2, %3}, {%4, %5, %6, %7}, {%8, %9}, {%0, %1, %2, %3};"
        : "+f"(d[0]), "+f"(d[1]), "+f"(d[2]), "+f"(d[3])
        : "r"(a0), "r"(a1), "r"(a2), "r"(a3), "r"(b0), "r"(b1));
}

// ============================================================================
// prep 1: A[n][f] = fp16(C[f][n] * W[n])
// ============================================================================
__global__ void prep_a_kernel(const float* __restrict__ C,
                              const float* __restrict__ W) {
    __shared__ float tile[32][33];
    const int n0 = blockIdx.x * 32;
    const int f0 = blockIdx.y * 32;
    const int tx = threadIdx.x, ty = threadIdx.y;
    const float w = W[n0 + tx];
#pragma unroll
    for (int i = 0; i < 32; i += 8)
        tile[ty + i][tx] = C[(size_t)(f0 + ty + i) * N_DIM + n0 + tx] * w;
    __syncthreads();
    if (tx < 16) {
#pragma unroll
        for (int i = 0; i < 32; i += 8) {
            const int n = n0 + ty + i;
            __half2 v = __floats2half2_rn(tile[2 * tx][ty + i],
                                          tile[2 * tx + 1][ty + i]);
            *reinterpret_cast<__half2*>(g_A + (size_t)n * F_DIM + f0 + 2 * tx) = v;
        }
    }
}

// ============================================================================
// prep 2: Xt[b][l][f] = fp16(X[b][f][l]); 64-f x 32-l tiles, 128B-coalesced
// writes (16B per thread), l zero-padded to 1024
// ============================================================================
__global__ void prep_x_kernel(const float* __restrict__ X) {
    __shared__ float tile[64][33];
    const int l0 = blockIdx.x * 32;
    const int f0 = blockIdx.y * 64;
    const int b  = blockIdx.z;
    const int tx = threadIdx.x, ty = threadIdx.y;
    const int tid = ty * 32 + tx;
    const float* Xb = X + (size_t)b * F_DIM * L_DIM;
    const int l = l0 + tx;
#pragma unroll
    for (int i = 0; i < 64; i += 8)
        tile[ty + i][tx] = (l < L_DIM)
            ? Xb[(size_t)(f0 + ty + i) * L_DIM + l] : 0.0f;
    __syncthreads();

    // write: 32 rows x 8 threads; each thread 8 halves (16B) contiguous
    const int row = tid >> 3;
    const int c8  = tid & 7;
    __half2 h[4];
#pragma unroll
    for (int m = 0; m < 4; m++)
        h[m] = __floats2half2_rn(tile[8 * c8 + 2 * m][row],
                                 tile[8 * c8 + 2 * m + 1][row]);
    __half* Xtb = g_Xt + (size_t)b * LPAD * F_DIM;
    *reinterpret_cast<int4*>(Xtb + (size_t)(l0 + row) * F_DIM + f0 + 8 * c8) =
        *reinterpret_cast<int4*>(h);
}

// ============================================================================
// GEMM: out[b, n0:+128, l0:+128] = A x Xt^T
//   128 threads = 4 warps: 2(m) x 2(n), warp tile 64 x 64
//   mma m16n8k16 f16.f32, ldmatrix fragments, 3-stage x 64-K cp.async,
//   one __syncthreads per 64-K chunk, 2 CTAs per SM
// ============================================================================
__global__ void __launch_bounds__(128, 2)
gemm_kernel(float* __restrict__ out) {
    extern __shared__ __align__(128) char smem[];
    const uint32_t sbase = smem_u32(smem);

    const int tid = threadIdx.x;
    const int wid = tid >> 5;
    const int lid = tid & 31;
    const int g = lid >> 2;
    const int t = lid & 3;

    const int wm = wid & 1;          // 0..1 -> 64 m-rows each
    const int wn = wid >> 1;         // 0..1 -> 64 n-cols each

    const int n0 = blockIdx.x * TM;
    const int l0 = blockIdx.y * TN;
    const int b  = blockIdx.z;

    const __half* Abase = g_A  + (size_t)n0 * F_DIM;
    const __half* Bbase = g_Xt + ((size_t)b * LPAD + l0) * F_DIM;

    float d[4][8][4];
#pragma unroll
    for (int mi = 0; mi < 4; mi++)
#pragma unroll
        for (int ni = 0; ni < 8; ni++)
#pragma unroll
            for (int r = 0; r < 4; r++) d[mi][ni][r] = 0.0f;

    // cp.async: thread tid owns row tid of A and row tid of B; 8 x 16B each
    auto load_stage = [&](int s, int k) {
        const int k0 = k * KC;
        const uint32_t sa = sbase + s * STAGE_BYTES;
        const uint32_t sb = sa + A_STAGE_BYTES;
        const __half* asrc = Abase + (size_t)tid * F_DIM + k0;
        const __half* bsrc = Bbase + (size_t)tid * F_DIM + k0;
#pragma unroll
        for (int c = 0; c < 8; c++)
            CP_ASYNC16(sa + tid * RSTRIDE_B + c * 16, asrc + c * 8);
#pragma unroll
        for (int c = 0; c < 8; c++)
            CP_ASYNC16(sb + tid * RSTRIDE_B + c * 16, bsrc + c * 8);
    };

    load_stage(0, 0); CP_COMMIT();
    load_stage(1, 1); CP_COMMIT();

    const int lrow = lid & 15;
    const int lchunk = (lid >> 4) * 16;

    for (int k = 0; k < KITERS; k++) {
        CP_WAIT(1);                  // chunk k resident (rigorous: 1 commit/iter)
        __syncthreads();             // all warps done with chunk k-1's slot
        if (k + 2 < KITERS) load_stage((k + 2) % STAGES, k + 2);
        CP_COMMIT();

        const uint32_t sa = sbase + (k % STAGES) * STAGE_BYTES;
        const uint32_t sb = sa + A_STAGE_BYTES;

#pragma unroll
        for (int kk = 0; kk < 4; kk++) {
            const uint32_t koff = kk * 32 + lchunk;
            uint32_t af[4][4];
#pragma unroll
            for (int mi = 0; mi < 4; mi++) {
                uint32_t addr = sa + (wm * 64 + mi * 16 + lrow) * RSTRIDE_B + koff;
                LDSM_X4(af[mi][0], af[mi][1], af[mi][2], af[mi][3], addr);
            }
            uint32_t bf[8][2];
#pragma unroll
            for (int p = 0; p < 4; p++) {
                uint32_t addr = sb + (wn * 64 + p * 16 + lrow) * RSTRIDE_B + koff;
                uint32_t m0, m1, m2, m3;
                LDSM_X4(m0, m1, m2, m3, addr);
                bf[2 * p][0] = m0; bf[2 * p][1] = m2;
                bf[2 * p + 1][0] = m1; bf[2 * p + 1][1] = m3;
            }
#pragma unroll
            for (int mi = 0; mi < 4; mi++)
#pragma unroll
                for (int ni = 0; ni < 8; ni++)
                    mma_f16(d[mi][ni], af[mi][0], af[mi][1], af[mi][2], af[mi][3],
                            bf[ni][0], bf[ni][1]);
        }
    }

    // ---- epilogue: direct global float2 stores ----
#pragma unroll
    for (int mi = 0; mi < 4; mi++) {
        const int row = n0 + wm * 64 + mi * 16 + g;
        float* r0 = out + ((size_t)b * N_DIM + row) * L_DIM;
        float* r1 = r0 + 8 * L_DIM;
#pragma unroll
        for (int ni = 0; ni < 8; ni++) {
            const int l = l0 + wn * 64 + ni * 8 + 2 * t;
            if (l < L_DIM) {
                *reinterpret_cast<float2*>(r0 + l) =
                    make_float2(d[mi][ni][0], d[mi][ni][1]);
                *reinterpret_cast<float2*>(r1 + l) =
                    make_float2(d[mi][ni][2], d[mi][ni][3]);
            }
        }
    }
}

// ============================================================================
// host
// ============================================================================
extern "C" void kernel_launch(void* const* d_in, const int* in_sizes, int n_in,
                              void* d_out, int out_size) {
    const float* X = (const float*)d_in[0];
    const float* C = (const float*)d_in[1];
    const float* W = (const float*)d_in[2];
    for (int i = 0; i < n_in; i++) {
        if (in_sizes[i] == B_DIM * F_DIM * L_DIM) X = (const float*)d_in[i];
        else if (in_sizes[i] == F_DIM * N_DIM)    C = (const float*)d_in[i];
        else if (in_sizes[i] == N_DIM)            W = (const float*)d_in[i];
    }

    cudaFuncSetAttribute(gemm_kernel,
                         cudaFuncAttributeMaxDynamicSharedMemorySize, SMEM_BYTES);

    prep_a_kernel<<<dim3(N_DIM / 32, F_DIM / 32), dim3(32, 8)>>>(C, W);
    prep_x_kernel<<<dim3(LPAD / 32, F_DIM / 64, B_DIM), dim3(32, 8)>>>(X);
    gemm_kernel<<<dim3(N_DIM / TM, LPAD / TN, B_DIM), 128, SMEM_BYTES>>>(
        (float*)d_out);
}

// round 8
// speedup vs baseline: 1.9795x; 1.4385x over previous
#include <cuda_runtime.h>
#include <cuda_fp16.h>
#include <cstdint>

// ============================================================================
// dims
// ============================================================================
#define B_DIM 32
#define F_DIM 1024
#define L_DIM 1000
#define N_DIM 2048
#define LPAD  1024

// GEMM tiling (per batch: M=N_DIM rows n, N=L cols l, K=F)  — R5 config
#define TM 128
#define TN 128
#define KC 32                    // K halves per stage (64B rows)
#define STAGES 4
#define KITERS (F_DIM / KC)      // 32

// SMEM: padded row stride 40 halves = 80B -> ldmatrix conflict-free
#define RSTRIDE_B 80
#define A_STAGE_BYTES (TM * RSTRIDE_B)                     // 10240
#define B_STAGE_BYTES (TN * RSTRIDE_B)                     // 10240
#define STAGE_BYTES (A_STAGE_BYTES + B_STAGE_BYTES)        // 20480
#define SMEM_BYTES (STAGES * STAGE_BYTES)                  // 81920

// ============================================================================
// device scratch (static globals: allocation-guard safe)
// ============================================================================
__device__ __align__(1024) __half g_A [(size_t)N_DIM * F_DIM];        // 4 MB
__device__ __align__(1024) __half g_Xt[(size_t)B_DIM * LPAD * F_DIM]; // 67 MB

// ============================================================================
// helpers
// ============================================================================
__device__ __forceinline__ uint32_t smem_u32(const void* p) {
    uint32_t a;
    asm("{ .reg .u64 t; cvta.to.shared.u64 t, %1; cvt.u32.u64 %0, t; }"
        : "=r"(a) : "l"(p));
    return a;
}

#define CP_ASYNC16(dst, src) \
    asm volatile("cp.async.cg.shared.global [%0], [%1], 16;" \
                 :: "r"(dst), "l"(src) : "memory")
#define CP_COMMIT() asm volatile("cp.async.commit_group;" ::: "memory")
#define CP_WAIT(n)  asm volatile("cp.async.wait_group %0;" :: "n"(n) : "memory")

#define LDSM_X4(r0, r1, r2, r3, addr) \
    asm volatile("ldmatrix.sync.aligned.m8n8.x4.shared.b16 {%0,%1,%2,%3}, [%4];" \
                 : "=r"(r0), "=r"(r1), "=r"(r2), "=r"(r3) : "r"(addr))

__device__ __forceinline__ void mma_f16(float d[4],
                                        uint32_t a0, uint32_t a1,
                                        uint32_t a2, uint32_t a3,
                                        uint32_t b0, uint32_t b1) {
    asm volatile(
        "mma.sync.aligned.m16n8k16.row.col.f32.f16.f16.f32 "
        "{%0, %1, %2, %3}, {%4, %5, %6, %7}, {%8, %9}, {%0, %1, %2, %3};"
        : "+f"(d[0]), "+f"(d[1]), "+f"(d[2]), "+f"(d[3])
        : "r"(a0), "r"(a1), "r"(a2), "r"(a3), "r"(b0), "r"(b1));
}

// ============================================================================
// prep 1: A[n][f] = fp16(C[f][n] * W[n])
// ============================================================================
__global__ void prep_a_kernel(const float* __restrict__ C,
                              const float* __restrict__ W) {
    __shared__ float tile[32][33];
    const int n0 = blockIdx.x * 32;
    const int f0 = blockIdx.y * 32;
    const int tx = threadIdx.x, ty = threadIdx.y;
    const float w = W[n0 + tx];
#pragma unroll
    for (int i = 0; i < 32; i += 8)
        tile[ty + i][tx] = C[(size_t)(f0 + ty + i) * N_DIM + n0 + tx] * w;
    __syncthreads();
    if (tx < 16) {
#pragma unroll
        for (int i = 0; i < 32; i += 8) {
            const int n = n0 + ty + i;
            __half2 v = __floats2half2_rn(tile[2 * tx][ty + i],
                                          tile[2 * tx + 1][ty + i]);
            *reinterpret_cast<__half2*>(g_A + (size_t)n * F_DIM + f0 + 2 * tx) = v;
        }
    }
}

// ============================================================================
// prep 2: Xt[b][l][f] = fp16(X[b][f][l]); 64-f x 32-l tiles, 128B-coalesced
// writes (16B per thread), l zero-padded to 1024
// ============================================================================
__global__ void prep_x_kernel(const float* __restrict__ X) {
    __shared__ float tile[64][33];
    const int l0 = blockIdx.x * 32;
    const int f0 = blockIdx.y * 64;
    const int b  = blockIdx.z;
    const int tx = threadIdx.x, ty = threadIdx.y;
    const int tid = ty * 32 + tx;
    const float* Xb = X + (size_t)b * F_DIM * L_DIM;
    const int l = l0 + tx;
#pragma unroll
    for (int i = 0; i < 64; i += 8)
        tile[ty + i][tx] = (l < L_DIM)
            ? Xb[(size_t)(f0 + ty + i) * L_DIM + l] : 0.0f;
    __syncthreads();

    // write: 32 rows x 8 threads; each thread 8 halves (16B) contiguous
    const int row = tid >> 3;
    const int c8  = tid & 7;
    __half2 h[4];
#pragma unroll
    for (int m = 0; m < 4; m++)
        h[m] = __floats2half2_rn(tile[8 * c8 + 2 * m][row],
                                 tile[8 * c8 + 2 * m + 1][row]);
    __half* Xtb = g_Xt + (size_t)b * LPAD * F_DIM;
    *reinterpret_cast<int4*>(Xtb + (size_t)(l0 + row) * F_DIM + f0 + 8 * c8) =
        *reinterpret_cast<int4*>(h);
}

// ============================================================================
// GEMM (R5 config): out[b, n0:+128, l0:+128] = A x Xt^T
//   128 threads = 4 warps: 2(m) x 2(n), warp tile 64 x 64
//   mma m16n8k16 f16.f32, ldmatrix fragments, 4-stage cp.async,
//   one __syncthreads per k-chunk, 2 CTAs per SM
// ============================================================================
__global__ void __launch_bounds__(128, 2)
gemm_kernel(float* __restrict__ out) {
    extern __shared__ __align__(128) char smem[];
    const uint32_t sbase = smem_u32(smem);

    const int tid = threadIdx.x;
    const int wid = tid >> 5;
    const int lid = tid & 31;
    const int g = lid >> 2;
    const int t = lid & 3;

    const int wm = wid & 1;          // 0..1 -> 64 m-rows each
    const int wn = wid >> 1;         // 0..1 -> 64 n-cols each

    const int n0 = blockIdx.x * TM;
    const int l0 = blockIdx.y * TN;
    const int b  = blockIdx.z;

    const __half* Abase = g_A  + (size_t)n0 * F_DIM;
    const __half* Bbase = g_Xt + ((size_t)b * LPAD + l0) * F_DIM;

    float d[4][8][4];
#pragma unroll
    for (int mi = 0; mi < 4; mi++)
#pragma unroll
        for (int ni = 0; ni < 8; ni++)
#pragma unroll
            for (int r = 0; r < 4; r++) d[mi][ni][r] = 0.0f;

    // cp.async mapping: 128 threads cover 128 rows x 4 chunks (16B) per matrix
    const int c_row = tid >> 2;      // 0..31, +32 per i
    const int c_cb  = tid & 3;

    auto load_stage = [&](int s, int k) {
        const int k0 = k * KC;
        const uint32_t sa = sbase + s * STAGE_BYTES;
        const uint32_t sb = sa + A_STAGE_BYTES;
#pragma unroll
        for (int i = 0; i < 4; i++) {
            int row = c_row + i * 32;
            CP_ASYNC16(sa + row * RSTRIDE_B + c_cb * 16,
                       Abase + (size_t)row * F_DIM + k0 + c_cb * 8);
        }
#pragma unroll
        for (int i = 0; i < 4; i++) {
            int row = c_row + i * 32;
            CP_ASYNC16(sb + row * RSTRIDE_B + c_cb * 16,
                       Bbase + (size_t)row * F_DIM + k0 + c_cb * 8);
        }
        CP_COMMIT();
    };

    // prologue: stages 0..2
    load_stage(0, 0);
    load_stage(1, 1);
    load_stage(2, 2);

    const int lrow = lid & 15;
    const int lchunk = (lid >> 4) * 16;

    for (int k = 0; k < KITERS; k++) {
        CP_WAIT(2);                  // stage k resident
        __syncthreads();             // all warps done with stage (k-1)%4
        if (k + 3 < KITERS) load_stage((k + 3) % STAGES, k + 3);

        const uint32_t sa = sbase + (k % STAGES) * STAGE_BYTES;
        const uint32_t sb = sa + A_STAGE_BYTES;

#pragma unroll
        for (int kk = 0; kk < 2; kk++) {
            const uint32_t koff = kk * 32 + lchunk;
            uint32_t af[4][4];
#pragma unroll
            for (int mi = 0; mi < 4; mi++) {
                uint32_t addr = sa + (wm * 64 + mi * 16 + lrow) * RSTRIDE_B + koff;
                LDSM_X4(af[mi][0], af[mi][1], af[mi][2], af[mi][3], addr);
            }
            uint32_t bf[8][2];
#pragma unroll
            for (int p = 0; p < 4; p++) {
                uint32_t addr = sb + (wn * 64 + p * 16 + lrow) * RSTRIDE_B + koff;
                uint32_t m0, m1, m2, m3;
                LDSM_X4(m0, m1, m2, m3, addr);
                bf[2 * p][0] = m0; bf[2 * p][1] = m2;
                bf[2 * p + 1][0] = m1; bf[2 * p + 1][1] = m3;
            }
#pragma unroll
            for (int mi = 0; mi < 4; mi++)
#pragma unroll
                for (int ni = 0; ni < 8; ni++)
                    mma_f16(d[mi][ni], af[mi][0], af[mi][1], af[mi][2], af[mi][3],
                            bf[ni][0], bf[ni][1]);
        }
    }

    // ---- epilogue: direct global float2 stores ----
#pragma unroll
    for (int mi = 0; mi < 4; mi++) {
        const int row = n0 + wm * 64 + mi * 16 + g;
        float* r0 = out + ((size_t)b * N_DIM + row) * L_DIM;
        float* r1 = r0 + 8 * L_DIM;
#pragma unroll
        for (int ni = 0; ni < 8; ni++) {
            const int l = l0 + wn * 64 + ni * 8 + 2 * t;
            if (l < L_DIM) {
                *reinterpret_cast<float2*>(r0 + l) =
                    make_float2(d[mi][ni][0], d[mi][ni][1]);
                *reinterpret_cast<float2*>(r1 + l) =
                    make_float2(d[mi][ni][2], d[mi][ni][3]);
            }
        }
    }
}

// ============================================================================
// host
// ============================================================================
extern "C" void kernel_launch(void* const* d_in, const int* in_sizes, int n_in,
                              void* d_out, int out_size) {
    const float* X = (const float*)d_in[0];
    const float* C = (const float*)d_in[1];
    const float* W = (const float*)d_in[2];
    for (int i = 0; i < n_in; i++) {
        if (in_sizes[i] == B_DIM * F_DIM * L_DIM) X = (const float*)d_in[i];
        else if (in_sizes[i] == F_DIM * N_DIM)    C = (const float*)d_in[i];
        else if (in_sizes[i] == N_DIM)            W = (const float*)d_in[i];
    }

    cudaFuncSetAttribute(gemm_kernel,
                         cudaFuncAttributeMaxDynamicSharedMemorySize, SMEM_BYTES);

    prep_a_kernel<<<dim3(N_DIM / 32, F_DIM / 32), dim3(32, 8)>>>(C, W);
    prep_x_kernel<<<dim3(LPAD / 32, F_DIM / 64, B_DIM), dim3(32, 8)>>>(X);
    gemm_kernel<<<dim3(N_DIM / TM, LPAD / TN, B_DIM), 128, SMEM_BYTES>>>(
        (float*)d_out);
}